// round 1
// baseline (speedup 1.0000x reference)
#include <cuda_runtime.h>
#include <math.h>

// ---------------- constants ----------------
constexpr int cB = 32, cN = 32, cE = 64, cW = 40, cHgrid = 40, cHW = 1600;
constexpr int cD = 256, cNH = 8, cDH = 32, cL = 6;
constexpr int cTn = cB * cN;          // 1024
constexpr int cTe = cB * cE;          // 2048
constexpr int cT  = cTn + cTe;        // 3072
constexpr int cTB = cN + cE;          // 96 tokens per batch
constexpr int cFF = 1024;
constexpr int cFKV = cB * cHW;        // 51200
constexpr int SPLITS = 8;
constexpr int KSPLIT = cHW / SPLITS;  // 200
constexpr int KTILE = 64;
constexpr float ATTN_SCALE = 0.17677669529663689f; // 1/sqrt(32)
constexpr float LOG1E4 = 9.210340371976184f;

// ---------------- scratch arena ----------------
constexpr size_t SZ_TD = (size_t)cT * cD;           // 786432
constexpr size_t O_Q    = 0;
constexpr size_t O_X    = O_Q    + SZ_TD;
constexpr size_t O_XE   = O_X    + SZ_TD;
constexpr size_t O_TMP  = O_XE   + SZ_TD;
constexpr size_t O_QH   = O_TMP  + SZ_TD;
constexpr size_t O_AO   = O_QH   + SZ_TD;
constexpr size_t O_EMB  = O_AO   + SZ_TD;
constexpr size_t O_BIAS = O_EMB  + SZ_TD;                       // cT*cHW
constexpr size_t O_KH   = O_BIAS + (size_t)cT * cHW;            // cFKV*cD
constexpr size_t O_VH   = O_KH   + (size_t)cFKV * cD;
constexpr size_t O_Y1   = O_VH   + (size_t)cFKV * cD;           // cT*cFF
constexpr size_t O_HN   = O_Y1   + (size_t)cT * cFF;            // cTn*cD
constexpr size_t O_EE   = O_HN   + (size_t)cTn * cD;            // cTe*cD
constexpr size_t O_NAGG = O_EE   + (size_t)cTe * cD;            // cTn*cD
constexpr size_t O_PM   = O_NAGG + (size_t)cTn * cD;            // B*NH*TB*SPLITS
constexpr size_t SZ_P   = (size_t)cB * cNH * cTB * SPLITS;      // 196608
constexpr size_t O_PDEN = O_PM   + SZ_P;
constexpr size_t O_PACC = O_PDEN + SZ_P;                        // SZ_P*cDH
constexpr size_t O_TOTAL = O_PACC + SZ_P * cDH;

__device__ __align__(16) float g_buf[O_TOTAL];
__device__ int   g_src[cTe];
__device__ int   g_dst[cTe];
__device__ float g_logits[cTe * cNH];
__device__ float g_exl[cTe * cNH];
__device__ float g_m[cTn * cNH];
__device__ float g_den[cTn * cNH];

// ---------------- helpers ----------------
__device__ __forceinline__ int row_of(int b, int t) {
    return (t < cN) ? b * cN + t : cTn + b * cE + (t - cN);
}

__device__ __forceinline__ void atomicMaxF(float* addr, float val) {
    int old = __float_as_int(*addr);
    while (__int_as_float(old) < val) {
        int prev = atomicCAS((int*)addr, old, __float_as_int(val));
        if (prev == old) break;
        old = prev;
    }
}

// ---------------- precompute kernels ----------------
__global__ void k_edges(const int* __restrict__ el) {
    int e = blockIdx.x * blockDim.x + threadIdx.x;
    if (e < cTe) {
        int b = e / cE;
        g_src[e] = el[e] + b * cN;
        g_dst[e] = el[cTe + e] + b * cN;
    }
}

__global__ void k_node_heat(const float* __restrict__ boxes) {
    int nd = blockIdx.x;
    int t = threadIdx.x;
    __shared__ float hx[cW], hy[cHgrid];
    float cx = boxes[nd * 4 + 0], cy = boxes[nd * 4 + 1];
    float w  = boxes[nd * 4 + 2], h  = boxes[nd * 4 + 3];
    if (t < cW) {
        float gx = (t + 0.5f) / cW;
        float dd = gx - cx;
        hx[t] = expf(-dd * dd / (0.5f * w * w + 1e-6f));
    } else if (t < cW + cHgrid) {
        int y = t - cW;
        float gy = (y + 0.5f) / cHgrid;
        float dd = gy - cy;
        hy[y] = expf(-dd * dd / (0.5f * h * h + 1e-6f));
    }
    __syncthreads();
    float* out = g_buf + O_BIAS + (size_t)nd * cHW;
    for (int i = t; i < cHW; i += blockDim.x)
        out[i] = hy[i / cW] * hx[i % cW];
}

__global__ void k_edge_heat(const float* __restrict__ boxes) {
    int e = blockIdx.x;
    int t = threadIdx.x;
    int s = g_src[e], d = g_dst[e];
    float c1x = boxes[s*4+0], c1y = boxes[s*4+1], w1 = boxes[s*4+2], h1 = boxes[s*4+3];
    float c2x = boxes[d*4+0], c2y = boxes[d*4+1], w2 = boxes[d*4+2], h2 = boxes[d*4+3];
    float ux1 = fminf(c1x - w1*0.5f, c2x - w2*0.5f);
    float uy1 = fminf(c1y - h1*0.5f, c2y - h2*0.5f);
    float ux2 = fmaxf(c1x + w1*0.5f, c2x + w2*0.5f);
    float uy2 = fmaxf(c1y + h1*0.5f, c2y + h2*0.5f);
    float ucx = (ux1 + ux2) * 0.5f, ucy = (uy1 + uy2) * 0.5f;
    float uw = ux2 - ux1, uh = uy2 - uy1;
    __shared__ float hx[cW], hy[cHgrid];
    if (t < cW) {
        float gx = (t + 0.5f) / cW;
        float dd = gx - ucx;
        hx[t] = expf(-dd * dd / (0.5f * uw * uw + 1e-6f));
    } else if (t < cW + cHgrid) {
        int y = t - cW;
        float gy = (y + 0.5f) / cHgrid;
        float dd = gy - ucy;
        hy[y] = expf(-dd * dd / (0.5f * uh * uh + 1e-6f));
    }
    __syncthreads();
    const float* hs = g_buf + O_BIAS + (size_t)s * cHW;
    const float* hd = g_buf + O_BIAS + (size_t)d * cHW;
    float* out = g_buf + O_BIAS + (size_t)(cTn + e) * cHW;
    for (int i = t; i < cHW; i += blockDim.x) {
        float u = hy[i / cW] * hx[i % cW];
        out[i] = fmaxf(fmaxf(hs[i], hd[i]), u);
    }
}

__global__ void k_emb(const float* __restrict__ boxes) {
    int i = blockIdx.x * blockDim.x + threadIdx.x;
    if (i >= cT * cD) return;
    int r = i / cD, ch = i % cD;
    int c = ch >> 6;           // which coord
    int j = ch & 63;           // pos in 64-dim sinus
    int fj = j & 31;
    float v;
    if (r < cTn) {
        v = boxes[r * 4 + c];
    } else {
        int e = r - cTn;
        v = boxes[g_src[e] * 4 + c] - boxes[g_dst[e] * 4 + c];
    }
    float fr = expf(-LOG1E4 * (float)fj / 32.0f);
    float ang = v * fr;
    g_buf[O_EMB + i] = (j < 32) ? sinf(ang) : cosf(ang);
}

// ---------------- generic kernels ----------------
__global__ void k_copy(float* __restrict__ dst, const float* __restrict__ src, int n) {
    int i = blockIdx.x * blockDim.x + threadIdx.x;
    if (i < n) dst[i] = src[i];
}
__global__ void k_fill(float* __restrict__ p, float v, int n) {
    int i = blockIdx.x * blockDim.x + threadIdx.x;
    if (i < n) p[i] = v;
}
__global__ void k_vadd(float* __restrict__ o, const float* __restrict__ a,
                       const float* __restrict__ b, int n) {
    int i = blockIdx.x * blockDim.x + threadIdx.x;
    if (i < n) o[i] = a[i] + b[i];
}
__global__ void k_res_add(float* __restrict__ q, const float* __restrict__ t,
                          const float* __restrict__ ls, int n) {
    int i = blockIdx.x * blockDim.x + threadIdx.x;
    if (i < n) q[i] += ls[i & (cD - 1)] * t[i];
}
__global__ void k_res_fromx(float* __restrict__ q, const float* __restrict__ x,
                            const float* __restrict__ t, const float* __restrict__ ls, int n) {
    int i = blockIdx.x * blockDim.x + threadIdx.x;
    if (i < n) q[i] = x[i] + ls[i & (cD - 1)] * t[i];
}
__global__ void k_gelu(float* __restrict__ y, int n) {
    int i = blockIdx.x * blockDim.x + threadIdx.x;
    if (i < n) {
        float v = y[i];
        y[i] = 0.5f * v * (1.0f + erff(v * 0.70710678118654752f));
    }
}

// LayerNorm: one block (256 threads) per row of 256
__global__ void k_ln(const float* __restrict__ in, const float* __restrict__ g,
                     const float* __restrict__ bt, float* __restrict__ out) {
    int r = blockIdx.x, t = threadIdx.x;
    float v = in[r * cD + t];
    __shared__ float red[8];
    __shared__ float stat;
    float s = v;
    #pragma unroll
    for (int o = 16; o > 0; o >>= 1) s += __shfl_down_sync(0xffffffffu, s, o);
    if ((t & 31) == 0) red[t >> 5] = s;
    __syncthreads();
    if (t == 0) {
        float tot = 0;
        #pragma unroll
        for (int i = 0; i < 8; i++) tot += red[i];
        stat = tot * (1.0f / cD);
    }
    __syncthreads();
    float mean = stat;
    float dlt = v - mean;
    float s2 = dlt * dlt;
    __syncthreads();
    #pragma unroll
    for (int o = 16; o > 0; o >>= 1) s2 += __shfl_down_sync(0xffffffffu, s2, o);
    if ((t & 31) == 0) red[t >> 5] = s2;
    __syncthreads();
    if (t == 0) {
        float tot = 0;
        #pragma unroll
        for (int i = 0; i < 8; i++) tot += red[i];
        stat = tot * (1.0f / cD);
    }
    __syncthreads();
    out[r * cD + t] = dlt * rsqrtf(stat + 1e-5f) * g[t] + bt[t];
}

// ---------------- tiled SGEMM: C = A * op(B) (+bias) ----------------
// TB=true : B is [N,K] row-major, C[m,n] = sum_k A[m,k]*B[n,k]
// TB=false: B is [K,N] row-major, C[m,n] = sum_k A[m,k]*B[k,n]
// Requires M%64==0, N%64==0, K%16==0, 16B-aligned pointers.
template <bool TB, bool BIAS>
__global__ void __launch_bounds__(256) k_sgemm(const float* __restrict__ A,
                                               const float* __restrict__ Bw,
                                               const float* __restrict__ bias,
                                               float* __restrict__ C,
                                               int M, int N, int K) {
    __shared__ float As[16][64];
    __shared__ float Bs[16][64];
    int tid = threadIdx.x;
    int tx = tid & 15, ty = tid >> 4;
    int m0 = blockIdx.y * 64, n0 = blockIdx.x * 64;
    float acc[4][4] = {};
    int ai = tid >> 2;
    int aj = (tid & 3) * 4;
    int bi, bj;
    if (TB) { bi = tid >> 2; bj = (tid & 3) * 4; }
    else    { bi = tid >> 4; bj = (tid & 15) * 4; }
    for (int k0 = 0; k0 < K; k0 += 16) {
        float4 av = *(const float4*)(A + (size_t)(m0 + ai) * K + k0 + aj);
        As[aj + 0][ai] = av.x; As[aj + 1][ai] = av.y;
        As[aj + 2][ai] = av.z; As[aj + 3][ai] = av.w;
        if (TB) {
            float4 bv = *(const float4*)(Bw + (size_t)(n0 + bi) * K + k0 + bj);
            Bs[bj + 0][bi] = bv.x; Bs[bj + 1][bi] = bv.y;
            Bs[bj + 2][bi] = bv.z; Bs[bj + 3][bi] = bv.w;
        } else {
            float4 bv = *(const float4*)(Bw + (size_t)(k0 + bi) * N + n0 + bj);
            *(float4*)&Bs[bi][bj] = bv;
        }
        __syncthreads();
        #pragma unroll
        for (int kk = 0; kk < 16; kk++) {
            float a0 = As[kk][ty * 4 + 0], a1 = As[kk][ty * 4 + 1];
            float a2 = As[kk][ty * 4 + 2], a3 = As[kk][ty * 4 + 3];
            float b0 = Bs[kk][tx * 4 + 0], b1 = Bs[kk][tx * 4 + 1];
            float b2 = Bs[kk][tx * 4 + 2], b3 = Bs[kk][tx * 4 + 3];
            acc[0][0] += a0 * b0; acc[0][1] += a0 * b1; acc[0][2] += a0 * b2; acc[0][3] += a0 * b3;
            acc[1][0] += a1 * b0; acc[1][1] += a1 * b1; acc[1][2] += a1 * b2; acc[1][3] += a1 * b3;
            acc[2][0] += a2 * b0; acc[2][1] += a2 * b1; acc[2][2] += a2 * b2; acc[2][3] += a2 * b3;
            acc[3][0] += a3 * b0; acc[3][1] += a3 * b1; acc[3][2] += a3 * b2; acc[3][3] += a3 * b3;
        }
        __syncthreads();
    }
    #pragma unroll
    for (int i = 0; i < 4; i++) {
        int row = m0 + ty * 4 + i;
        #pragma unroll
        for (int j = 0; j < 4; j++) {
            int col = n0 + tx * 4 + j;
            float v = acc[i][j];
            if (BIAS) v += bias[col];
            C[(size_t)row * N + col] = v;
        }
    }
}

// ---------------- attention (flash-style, key-split) ----------------
__global__ void __launch_bounds__(96) k_attn_partial() {
    int h = blockIdx.x, b = blockIdx.y, s = blockIdx.z;
    int q = threadIdx.x; // 0..95
    __shared__ float ks[KTILE][cDH];
    __shared__ float vs[KTILE][cDH];
    const float* qh = g_buf + O_QH;
    const float* kh = g_buf + O_KH;
    const float* vh = g_buf + O_VH;
    int r = row_of(b, q);
    float qreg[cDH];
    #pragma unroll
    for (int d = 0; d < cDH; d++) qreg[d] = qh[r * cD + h * cDH + d];
    const float* brow = g_buf + O_BIAS + (size_t)r * cHW;
    float m = -INFINITY, den = 0.f;
    float acc[cDH];
    #pragma unroll
    for (int d = 0; d < cDH; d++) acc[d] = 0.f;
    int kbeg = s * KSPLIT;
    for (int k0 = kbeg; k0 < kbeg + KSPLIT; k0 += KTILE) {
        int kt = min(KTILE, kbeg + KSPLIT - k0);
        __syncthreads();
        for (int idx = q; idx < kt * cDH; idx += 96) {
            int kk = idx >> 5, d = idx & 31;
            int gi = (b * cHW + k0 + kk) * cD + h * cDH + d;
            ks[kk][d] = kh[gi];
            vs[kk][d] = vh[gi];
        }
        __syncthreads();
        for (int kk = 0; kk < kt; kk++) {
            float dot = 0.f;
            #pragma unroll
            for (int d = 0; d < cDH; d++) dot += qreg[d] * ks[kk][d];
            float sc = dot * ATTN_SCALE + brow[k0 + kk];
            if (sc <= m) {
                float p = __expf(sc - m);
                den += p;
                #pragma unroll
                for (int d = 0; d < cDH; d++) acc[d] += p * vs[kk][d];
            } else {
                float c = __expf(m - sc);
                m = sc;
                den = den * c + 1.f;
                #pragma unroll
                for (int d = 0; d < cDH; d++) acc[d] = acc[d] * c + vs[kk][d];
            }
        }
    }
    int pidx = ((b * cNH + h) * cTB + q) * SPLITS + s;
    g_buf[O_PM + pidx] = m;
    g_buf[O_PDEN + pidx] = den;
    #pragma unroll
    for (int d = 0; d < cDH; d++) g_buf[O_PACC + (size_t)pidx * cDH + d] = acc[d];
}

__global__ void k_attn_merge() {
    int q = blockIdx.x, b = blockIdx.y;
    int t = threadIdx.x;
    int h = t >> 5, d = t & 31;
    int base = ((b * cNH + h) * cTB + q) * SPLITS;
    float M = -INFINITY;
    #pragma unroll
    for (int s = 0; s < SPLITS; s++) M = fmaxf(M, g_buf[O_PM + base + s]);
    float den = 0.f, a = 0.f;
    #pragma unroll
    for (int s = 0; s < SPLITS; s++) {
        float w = __expf(g_buf[O_PM + base + s] - M);
        den += g_buf[O_PDEN + base + s] * w;
        a += g_buf[O_PACC + (size_t)(base + s) * cDH + d] * w;
    }
    int r = row_of(b, q);
    g_buf[O_AO + (size_t)r * cD + t] = a / den;
}

// ---------------- GAT kernels ----------------
__global__ void k_gat_init() {
    int i = blockIdx.x * blockDim.x + threadIdx.x;
    if (i < cTn * cNH) {
        g_m[i] = -INFINITY;
        g_den[i] = 0.f;
    }
}

__global__ void k_gat_logits(const float* __restrict__ asrc, const float* __restrict__ adst,
                             const float* __restrict__ aedge) {
    int idx = blockIdx.x * blockDim.x + threadIdx.x;
    if (idx >= cTe * cNH) return;
    int e = idx >> 3, h = idx & 7;
    int s = g_src[e], d2 = g_dst[e];
    int base = h * cDH;
    const float* hn = g_buf + O_HN;
    const float* ee = g_buf + O_EE;
    float sum = 0.f;
    #pragma unroll
    for (int d = 0; d < cDH; d++) {
        sum += hn[s * cD + base + d] * asrc[base + d]
             + hn[d2 * cD + base + d] * adst[base + d]
             + ee[e * cD + base + d] * aedge[base + d];
    }
    float lg = (sum > 0.f) ? sum : 0.2f * sum;
    g_logits[idx] = lg;
    atomicMaxF(&g_m[d2 * cNH + h], lg);
}

__global__ void k_gat_ex() {
    int idx = blockIdx.x * blockDim.x + threadIdx.x;
    if (idx >= cTe * cNH) return;
    int e = idx >> 3, h = idx & 7;
    int d2 = g_dst[e];
    float ex = expf(g_logits[idx] - g_m[d2 * cNH + h]);
    g_exl[idx] = ex;
    atomicAdd(&g_den[d2 * cNH + h], ex);
}

__global__ void k_gat_scatter() {
    int e = blockIdx.x;
    int c = threadIdx.x;
    int h = c >> 5;
    int d2 = g_dst[e], s = g_src[e];
    float alpha = g_exl[e * cNH + h] / (g_den[d2 * cNH + h] + 1e-9f);
    const float* hn = g_buf + O_HN;
    const float* ee = g_buf + O_EE;
    atomicAdd(&g_buf[O_NAGG + (size_t)d2 * cD + c],
              alpha * (hn[s * cD + c] + ee[e * cD + c]));
}

// ---------------- host orchestration ----------------
static void sgemm_nt_b(const float* A, const float* Bw, const float* bias, float* C,
                       int M, int N, int K) {
    dim3 g(N / 64, M / 64);
    k_sgemm<true, true><<<g, 256>>>(A, Bw, bias, C, M, N, K);
}
static void sgemm_nn_b(const float* A, const float* Bw, const float* bias, float* C,
                       int M, int N, int K) {
    dim3 g(N / 64, M / 64);
    k_sgemm<false, true><<<g, 256>>>(A, Bw, bias, C, M, N, K);
}
static void sgemm_nn(const float* A, const float* Bw, float* C, int M, int N, int K) {
    dim3 g(N / 64, M / 64);
    k_sgemm<false, false><<<g, 256>>>(A, Bw, nullptr, C, M, N, K);
}

extern "C" void kernel_launch(void* const* d_in, const int* in_sizes, int n_in,
                              void* d_out, int out_size) {
    const float* features   = (const float*)d_in[0];
    const float* boxes      = (const float*)d_in[1];
    const int*   edge_local = (const int*)  d_in[2];
    const float* nodes0     = (const float*)d_in[3];
    const float* edges0     = (const float*)d_in[4];
    const float* ln1_g      = (const float*)d_in[5];
    const float* ln1_b      = (const float*)d_in[6];
    const float* attn_in_w  = (const float*)d_in[7];
    const float* attn_in_b  = (const float*)d_in[8];
    const float* attn_out_w = (const float*)d_in[9];
    const float* attn_out_b = (const float*)d_in[10];
    const float* ls1        = (const float*)d_in[11];
    const float* ln2_g      = (const float*)d_in[12];
    const float* ln2_b      = (const float*)d_in[13];
    const float* gat_wn     = (const float*)d_in[14];
    const float* gat_we     = (const float*)d_in[15];
    const float* gat_a_src  = (const float*)d_in[16];
    const float* gat_a_dst  = (const float*)d_in[17];
    const float* gat_a_edge = (const float*)d_in[18];
    const float* gat_wo     = (const float*)d_in[19];
    const float* gat_bo     = (const float*)d_in[20];
    const float* gat_woe    = (const float*)d_in[21];
    const float* gat_boe    = (const float*)d_in[22];
    const float* ls2        = (const float*)d_in[23];
    const float* ln3_g      = (const float*)d_in[24];
    const float* ln3_b      = (const float*)d_in[25];
    const float* ffn_w1     = (const float*)d_in[26];
    const float* ffn_b1     = (const float*)d_in[27];
    const float* ffn_w2     = (const float*)d_in[28];
    const float* ffn_b2     = (const float*)d_in[29];
    const float* ls3        = (const float*)d_in[30];

    float* buf = nullptr;
    cudaGetSymbolAddress((void**)&buf, g_buf);
    float* out = (float*)d_out;

    const int nTD = cT * cD;

    // -------- precompute --------
    k_edges<<<(cTe + 255) / 256, 256>>>(edge_local);
    k_node_heat<<<cTn, 256>>>(boxes);
    k_edge_heat<<<cTe, 256>>>(boxes);
    k_emb<<<nTD / 256, 256>>>(boxes);
    k_copy<<<(cTn * cD) / 256, 256>>>(buf + O_Q, nodes0, cTn * cD);
    k_copy<<<(cTe * cD) / 256, 256>>>(buf + O_Q + (size_t)cTn * cD, edges0, cTe * cD);

    for (int l = 0; l < cL; l++) {
        const float* Wqkv = attn_in_w + (size_t)l * 3 * cD * cD;
        const float* bqkv = attn_in_b + (size_t)l * 3 * cD;

        // ---- cross attention ----
        k_ln<<<cT, 256>>>(buf + O_Q, ln1_g + l * cD, ln1_b + l * cD, buf + O_X);
        sgemm_nt_b(buf + O_X, Wqkv, bqkv, buf + O_QH, cT, cD, cD);
        sgemm_nt_b(features, Wqkv + cD * cD, bqkv + cD, buf + O_KH, cFKV, cD, cD);
        sgemm_nt_b(features, Wqkv + 2 * cD * cD, bqkv + 2 * cD, buf + O_VH, cFKV, cD, cD);
        k_attn_partial<<<dim3(cNH, cB, SPLITS), 96>>>();
        k_attn_merge<<<dim3(cTB, cB), 256>>>();
        sgemm_nt_b(buf + O_AO, attn_out_w + (size_t)l * cD * cD,
                   attn_out_b + l * cD, buf + O_TMP, cT, cD, cD);
        k_res_add<<<nTD / 256, 256>>>(buf + O_Q, buf + O_TMP, ls1 + l * cD, nTD);

        // ---- GAT ----
        k_ln<<<cT, 256>>>(buf + O_Q, ln2_g + l * cD, ln2_b + l * cD, buf + O_X);
        k_vadd<<<nTD / 256, 256>>>(buf + O_XE, buf + O_X, buf + O_EMB, nTD);
        sgemm_nn(buf + O_XE, gat_wn + (size_t)l * cD * cD, buf + O_HN, cTn, cD, cD);
        sgemm_nn(buf + O_XE + (size_t)cTn * cD, gat_we + (size_t)l * cD * cD,
                 buf + O_EE, cTe, cD, cD);
        k_gat_init<<<(cTn * cNH + 255) / 256, 256>>>();
        k_fill<<<(cTn * cD) / 256, 256>>>(buf + O_NAGG, 0.f, cTn * cD);
        k_gat_logits<<<(cTe * cNH) / 256, 256>>>(gat_a_src + l * cD, gat_a_dst + l * cD,
                                                 gat_a_edge + l * cD);
        k_gat_ex<<<(cTe * cNH) / 256, 256>>>();
        k_gat_scatter<<<cTe, 256>>>();
        sgemm_nn_b(buf + O_NAGG, gat_wo + (size_t)l * cD * cD, gat_bo + l * cD,
                   buf + O_TMP, cTn, cD, cD);
        sgemm_nn_b(buf + O_EE, gat_woe + (size_t)l * cD * cD, gat_boe + l * cD,
                   buf + O_TMP + (size_t)cTn * cD, cTe, cD, cD);
        k_res_fromx<<<nTD / 256, 256>>>(buf + O_Q, buf + O_X, buf + O_TMP, ls2 + l * cD, nTD);

        // ---- FFN ----
        k_ln<<<cT, 256>>>(buf + O_Q, ln3_g + l * cD, ln3_b + l * cD, buf + O_X);
        sgemm_nn_b(buf + O_X, ffn_w1 + (size_t)l * cD * cFF, ffn_b1 + l * cFF,
                   buf + O_Y1, cT, cFF, cD);
        k_gelu<<<(cT * cFF) / 256, 256>>>(buf + O_Y1, cT * cFF);
        sgemm_nn_b(buf + O_Y1, ffn_w2 + (size_t)l * cFF * cD, ffn_b2 + l * cD,
                   buf + O_TMP, cT, cD, cFF);
        k_res_add<<<nTD / 256, 256>>>(buf + O_Q, buf + O_TMP, ls3 + l * cD, nTD);

        // ---- emit layer output ----
        k_copy<<<nTD / 256, 256>>>(out + (size_t)l * nTD, buf + O_Q, nTD);
    }
    (void)in_sizes; (void)n_in; (void)out_size;
}

// round 2
// speedup vs baseline: 1.3465x; 1.3465x over previous
#include <cuda_runtime.h>
#include <math.h>

// ---------------- constants ----------------
constexpr int cB = 32, cN = 32, cE = 64, cW = 40, cHgrid = 40, cHW = 1600;
constexpr int cD = 256, cNH = 8, cDH = 32, cL = 6;
constexpr int cTn = cB * cN;          // 1024
constexpr int cTe = cB * cE;          // 2048
constexpr int cT  = cTn + cTe;        // 3072
constexpr int cTB = cN + cE;          // 96 tokens per batch
constexpr int cFF = 1024;
constexpr int cFKV = cB * cHW;        // 51200
constexpr int SPLITS = 8;
constexpr int KSPLIT = cHW / SPLITS;  // 200
constexpr int KTILE = 64;
constexpr float ATTN_SCALE = 0.17677669529663689f; // 1/sqrt(32)
constexpr float LOG1E4 = 9.210340371976184f;

// ---------------- scratch arena ----------------
constexpr size_t SZ_TD = (size_t)cT * cD;           // 786432
constexpr size_t O_Q    = 0;
constexpr size_t O_X    = O_Q    + SZ_TD;
constexpr size_t O_XE   = O_X    + SZ_TD;
constexpr size_t O_TMP  = O_XE   + SZ_TD;
constexpr size_t O_QH   = O_TMP  + SZ_TD;
constexpr size_t O_AO   = O_QH   + SZ_TD;
constexpr size_t O_EMB  = O_AO   + SZ_TD;
constexpr size_t O_BIAS = O_EMB  + SZ_TD;                       // cT*cHW
constexpr size_t O_KH   = O_BIAS + (size_t)cT * cHW;            // cFKV*512 (packed K|V)
constexpr size_t O_Y1   = O_KH   + (size_t)cFKV * 512;          // cT*cFF
constexpr size_t O_HN   = O_Y1   + (size_t)cT * cFF;            // cTn*cD
constexpr size_t O_EE   = O_HN   + (size_t)cTn * cD;            // cTe*cD
constexpr size_t O_NAGG = O_EE   + (size_t)cTe * cD;            // cTn*cD
constexpr size_t O_PM   = O_NAGG + (size_t)cTn * cD;            // B*NH*TB*SPLITS
constexpr size_t SZ_P   = (size_t)cB * cNH * cTB * SPLITS;      // 196608
constexpr size_t O_PDEN = O_PM   + SZ_P;
constexpr size_t O_PACC = O_PDEN + SZ_P;                        // SZ_P*cDH
constexpr size_t O_TOTAL = O_PACC + SZ_P * cDH;

__device__ __align__(16) float g_buf[O_TOTAL];
__device__ int   g_src[cTe];
__device__ int   g_dst[cTe];
__device__ float g_logits[cTe * cNH];
__device__ float g_exl[cTe * cNH];
__device__ float g_m[cTn * cNH];
__device__ float g_den[cTn * cNH];

// ---------------- helpers ----------------
__device__ __forceinline__ int row_of(int b, int t) {
    return (t < cN) ? b * cN + t : cTn + b * cE + (t - cN);
}

__device__ __forceinline__ void atomicMaxF(float* addr, float val) {
    int old = __float_as_int(*addr);
    while (__int_as_float(old) < val) {
        int prev = atomicCAS((int*)addr, old, __float_as_int(val));
        if (prev == old) break;
        old = prev;
    }
}

__device__ __forceinline__ unsigned f2tf(float x) {
    unsigned r;
    asm("cvt.rna.tf32.f32 %0, %1;" : "=r"(r) : "f"(x));
    return r;
}

__device__ __forceinline__ void mma8(float* c, const unsigned* a, const unsigned* b) {
    asm volatile(
        "mma.sync.aligned.m16n8k8.row.col.f32.tf32.tf32.f32 "
        "{%0,%1,%2,%3}, {%4,%5,%6,%7}, {%8,%9}, {%0,%1,%2,%3};"
        : "+f"(c[0]), "+f"(c[1]), "+f"(c[2]), "+f"(c[3])
        : "r"(a[0]), "r"(a[1]), "r"(a[2]), "r"(a[3]), "r"(b[0]), "r"(b[1]));
}

// ---------------- precompute kernels ----------------
__global__ void k_edges(const int* __restrict__ el) {
    int e = blockIdx.x * blockDim.x + threadIdx.x;
    if (e < cTe) {
        int b = e / cE;
        g_src[e] = el[e] + b * cN;
        g_dst[e] = el[cTe + e] + b * cN;
    }
}

__global__ void k_node_heat(const float* __restrict__ boxes) {
    int nd = blockIdx.x;
    int t = threadIdx.x;
    __shared__ float hx[cW], hy[cHgrid];
    float cx = boxes[nd * 4 + 0], cy = boxes[nd * 4 + 1];
    float w  = boxes[nd * 4 + 2], h  = boxes[nd * 4 + 3];
    if (t < cW) {
        float gx = (t + 0.5f) / cW;
        float dd = gx - cx;
        hx[t] = expf(-dd * dd / (0.5f * w * w + 1e-6f));
    } else if (t < cW + cHgrid) {
        int y = t - cW;
        float gy = (y + 0.5f) / cHgrid;
        float dd = gy - cy;
        hy[y] = expf(-dd * dd / (0.5f * h * h + 1e-6f));
    }
    __syncthreads();
    float* out = g_buf + O_BIAS + (size_t)nd * cHW;
    for (int i = t; i < cHW; i += blockDim.x)
        out[i] = hy[i / cW] * hx[i % cW];
}

__global__ void k_edge_heat(const float* __restrict__ boxes) {
    int e = blockIdx.x;
    int t = threadIdx.x;
    int s = g_src[e], d = g_dst[e];
    float c1x = boxes[s*4+0], c1y = boxes[s*4+1], w1 = boxes[s*4+2], h1 = boxes[s*4+3];
    float c2x = boxes[d*4+0], c2y = boxes[d*4+1], w2 = boxes[d*4+2], h2 = boxes[d*4+3];
    float ux1 = fminf(c1x - w1*0.5f, c2x - w2*0.5f);
    float uy1 = fminf(c1y - h1*0.5f, c2y - h2*0.5f);
    float ux2 = fmaxf(c1x + w1*0.5f, c2x + w2*0.5f);
    float uy2 = fmaxf(c1y + h1*0.5f, c2y + h2*0.5f);
    float ucx = (ux1 + ux2) * 0.5f, ucy = (uy1 + uy2) * 0.5f;
    float uw = ux2 - ux1, uh = uy2 - uy1;
    __shared__ float hx[cW], hy[cHgrid];
    if (t < cW) {
        float gx = (t + 0.5f) / cW;
        float dd = gx - ucx;
        hx[t] = expf(-dd * dd / (0.5f * uw * uw + 1e-6f));
    } else if (t < cW + cHgrid) {
        int y = t - cW;
        float gy = (y + 0.5f) / cHgrid;
        float dd = gy - ucy;
        hy[y] = expf(-dd * dd / (0.5f * uh * uh + 1e-6f));
    }
    __syncthreads();
    const float* hs = g_buf + O_BIAS + (size_t)s * cHW;
    const float* hd = g_buf + O_BIAS + (size_t)d * cHW;
    float* out = g_buf + O_BIAS + (size_t)(cTn + e) * cHW;
    for (int i = t; i < cHW; i += blockDim.x) {
        float u = hy[i / cW] * hx[i % cW];
        out[i] = fmaxf(fmaxf(hs[i], hd[i]), u);
    }
}

__global__ void k_emb(const float* __restrict__ boxes) {
    int i = blockIdx.x * blockDim.x + threadIdx.x;
    if (i >= cT * cD) return;
    int r = i / cD, ch = i % cD;
    int c = ch >> 6;           // which coord
    int j = ch & 63;           // pos in 64-dim sinus
    int fj = j & 31;
    float v;
    if (r < cTn) {
        v = boxes[r * 4 + c];
    } else {
        int e = r - cTn;
        v = boxes[g_src[e] * 4 + c] - boxes[g_dst[e] * 4 + c];
    }
    float fr = expf(-LOG1E4 * (float)fj / 32.0f);
    float ang = v * fr;
    g_buf[O_EMB + i] = (j < 32) ? sinf(ang) : cosf(ang);
}

// ---------------- generic kernels ----------------
__global__ void k_copy(float* __restrict__ dst, const float* __restrict__ src, int n) {
    int i = blockIdx.x * blockDim.x + threadIdx.x;
    if (i < n) dst[i] = src[i];
}
__global__ void k_fill(float* __restrict__ p, float v, int n) {
    int i = blockIdx.x * blockDim.x + threadIdx.x;
    if (i < n) p[i] = v;
}
__global__ void k_vadd(float* __restrict__ o, const float* __restrict__ a,
                       const float* __restrict__ b, int n) {
    int i = blockIdx.x * blockDim.x + threadIdx.x;
    if (i < n) o[i] = a[i] + b[i];
}
__global__ void k_res_add(float* __restrict__ q, const float* __restrict__ t,
                          const float* __restrict__ ls, int n) {
    int i = blockIdx.x * blockDim.x + threadIdx.x;
    if (i < n) q[i] += ls[i & (cD - 1)] * t[i];
}
__global__ void k_res_fromx(float* __restrict__ q, const float* __restrict__ x,
                            const float* __restrict__ t, const float* __restrict__ ls, int n) {
    int i = blockIdx.x * blockDim.x + threadIdx.x;
    if (i < n) q[i] = x[i] + ls[i & (cD - 1)] * t[i];
}

// LayerNorm: one block (256 threads) per row of 256
__global__ void k_ln(const float* __restrict__ in, const float* __restrict__ g,
                     const float* __restrict__ bt, float* __restrict__ out) {
    int r = blockIdx.x, t = threadIdx.x;
    float v = in[r * cD + t];
    __shared__ float red[8];
    __shared__ float stat;
    float s = v;
    #pragma unroll
    for (int o = 16; o > 0; o >>= 1) s += __shfl_down_sync(0xffffffffu, s, o);
    if ((t & 31) == 0) red[t >> 5] = s;
    __syncthreads();
    if (t == 0) {
        float tot = 0;
        #pragma unroll
        for (int i = 0; i < 8; i++) tot += red[i];
        stat = tot * (1.0f / cD);
    }
    __syncthreads();
    float mean = stat;
    float dlt = v - mean;
    float s2 = dlt * dlt;
    __syncthreads();
    #pragma unroll
    for (int o = 16; o > 0; o >>= 1) s2 += __shfl_down_sync(0xffffffffu, s2, o);
    if ((t & 31) == 0) red[t >> 5] = s2;
    __syncthreads();
    if (t == 0) {
        float tot = 0;
        #pragma unroll
        for (int i = 0; i < 8; i++) tot += red[i];
        stat = tot * (1.0f / cD);
    }
    __syncthreads();
    out[r * cD + t] = dlt * rsqrtf(stat + 1e-5f) * g[t] + bt[t];
}

// ---------------- tf32 tensor-core GEMM ----------------
// C[M,N] = A[M,K] * op(B) (+bias) (+gelu)
// TB=true : B is [N,K] row-major (op = B^T)
// TB=false: B is [K,N] row-major
// Tiles: 128x64x16, 256 threads = 8 warps (4 along M x 2 along N), warp = 32x32.
// Requires M%128==0, N%64==0, K%16==0, 16B-aligned pointers.
template <bool TB, bool BIAS, bool GELU>
__global__ void __launch_bounds__(256) k_mma(const float* __restrict__ A,
                                             const float* __restrict__ Bw,
                                             const float* __restrict__ bias,
                                             float* __restrict__ C,
                                             int M, int N, int K) {
    __shared__ unsigned As[16][132];
    __shared__ unsigned Bs[16][68];
    const int tid = threadIdx.x;
    const int m0 = blockIdx.y * 128, n0 = blockIdx.x * 64;
    const int wid = tid >> 5, lane = tid & 31;
    const int wm = (wid & 3) * 32, wn = (wid >> 2) * 32;
    const int g = lane >> 2, tg = lane & 3;
    float c[2][4][4] = {};
    const int ar = tid >> 1, ac = (tid & 1) * 8;
    int br, bc;
    if (TB) { br = tid >> 2; bc = (tid & 3) * 4; }
    else    { br = tid >> 4; bc = (tid & 15) * 4; }

    for (int k0 = 0; k0 < K; k0 += 16) {
        #pragma unroll
        for (int h = 0; h < 2; h++) {
            float4 v = *(const float4*)(A + (size_t)(m0 + ar) * K + k0 + ac + h * 4);
            As[ac + h*4 + 0][ar] = f2tf(v.x);
            As[ac + h*4 + 1][ar] = f2tf(v.y);
            As[ac + h*4 + 2][ar] = f2tf(v.z);
            As[ac + h*4 + 3][ar] = f2tf(v.w);
        }
        if (TB) {
            float4 v = *(const float4*)(Bw + (size_t)(n0 + br) * K + k0 + bc);
            Bs[bc + 0][br] = f2tf(v.x);
            Bs[bc + 1][br] = f2tf(v.y);
            Bs[bc + 2][br] = f2tf(v.z);
            Bs[bc + 3][br] = f2tf(v.w);
        } else {
            float4 v = *(const float4*)(Bw + (size_t)(k0 + br) * N + n0 + bc);
            Bs[br][bc + 0] = f2tf(v.x);
            Bs[br][bc + 1] = f2tf(v.y);
            Bs[br][bc + 2] = f2tf(v.z);
            Bs[br][bc + 3] = f2tf(v.w);
        }
        __syncthreads();
        #pragma unroll
        for (int kk = 0; kk < 16; kk += 8) {
            unsigned a[2][4], b[4][2];
            #pragma unroll
            for (int i = 0; i < 2; i++) {
                int m = wm + i * 16 + g;
                a[i][0] = As[kk + tg][m];
                a[i][1] = As[kk + tg][m + 8];
                a[i][2] = As[kk + tg + 4][m];
                a[i][3] = As[kk + tg + 4][m + 8];
            }
            #pragma unroll
            for (int j = 0; j < 4; j++) {
                int n = wn + j * 8 + g;
                b[j][0] = Bs[kk + tg][n];
                b[j][1] = Bs[kk + tg + 4][n];
            }
            #pragma unroll
            for (int i = 0; i < 2; i++)
                #pragma unroll
                for (int j = 0; j < 4; j++)
                    mma8(c[i][j], a[i], b[j]);
        }
        __syncthreads();
    }
    #pragma unroll
    for (int i = 0; i < 2; i++) {
        #pragma unroll
        for (int j = 0; j < 4; j++) {
            int col = n0 + wn + j * 8 + tg * 2;
            #pragma unroll
            for (int p = 0; p < 4; p++) {
                int row = m0 + wm + i * 16 + g + ((p >= 2) ? 8 : 0);
                int cc = col + (p & 1);
                float v = c[i][j][p];
                if (BIAS) v += bias[cc];
                if (GELU) v = 0.5f * v * (1.0f + erff(v * 0.70710678118654752f));
                C[(size_t)row * N + cc] = v;
            }
        }
    }
}

// ---------------- attention (flash-style, key-split) ----------------
// K/V packed: row stride 512, K at +0, V at +256
__global__ void __launch_bounds__(96) k_attn_partial() {
    int h = blockIdx.x, b = blockIdx.y, s = blockIdx.z;
    int q = threadIdx.x; // 0..95
    __shared__ float ks[KTILE][cDH];
    __shared__ float vs[KTILE][cDH];
    const float* qh = g_buf + O_QH;
    const float* khv = g_buf + O_KH;
    int r = row_of(b, q);
    float qreg[cDH];
    #pragma unroll
    for (int d = 0; d < cDH; d++) qreg[d] = qh[r * cD + h * cDH + d];
    const float* brow = g_buf + O_BIAS + (size_t)r * cHW;
    float m = -INFINITY, den = 0.f;
    float acc[cDH];
    #pragma unroll
    for (int d = 0; d < cDH; d++) acc[d] = 0.f;
    int kbeg = s * KSPLIT;
    for (int k0 = kbeg; k0 < kbeg + KSPLIT; k0 += KTILE) {
        int kt = min(KTILE, kbeg + KSPLIT - k0);
        __syncthreads();
        for (int idx = q; idx < kt * cDH; idx += 96) {
            int kk = idx >> 5, d = idx & 31;
            size_t gi = (size_t)(b * cHW + k0 + kk) * 512 + h * cDH + d;
            ks[kk][d] = khv[gi];
            vs[kk][d] = khv[gi + 256];
        }
        __syncthreads();
        for (int kk = 0; kk < kt; kk++) {
            float dot = 0.f;
            #pragma unroll
            for (int d = 0; d < cDH; d++) dot += qreg[d] * ks[kk][d];
            float sc = dot * ATTN_SCALE + brow[k0 + kk];
            if (sc <= m) {
                float p = __expf(sc - m);
                den += p;
                #pragma unroll
                for (int d = 0; d < cDH; d++) acc[d] += p * vs[kk][d];
            } else {
                float cc = __expf(m - sc);
                m = sc;
                den = den * cc + 1.f;
                #pragma unroll
                for (int d = 0; d < cDH; d++) acc[d] = acc[d] * cc + vs[kk][d];
            }
        }
    }
    int pidx = ((b * cNH + h) * cTB + q) * SPLITS + s;
    g_buf[O_PM + pidx] = m;
    g_buf[O_PDEN + pidx] = den;
    #pragma unroll
    for (int d = 0; d < cDH; d++) g_buf[O_PACC + (size_t)pidx * cDH + d] = acc[d];
}

__global__ void k_attn_merge() {
    int q = blockIdx.x, b = blockIdx.y;
    int t = threadIdx.x;
    int h = t >> 5, d = t & 31;
    int base = ((b * cNH + h) * cTB + q) * SPLITS;
    float M = -INFINITY;
    #pragma unroll
    for (int s = 0; s < SPLITS; s++) M = fmaxf(M, g_buf[O_PM + base + s]);
    float den = 0.f, a = 0.f;
    #pragma unroll
    for (int s = 0; s < SPLITS; s++) {
        float w = __expf(g_buf[O_PM + base + s] - M);
        den += g_buf[O_PDEN + base + s] * w;
        a += g_buf[O_PACC + (size_t)(base + s) * cDH + d] * w;
    }
    int r = row_of(b, q);
    g_buf[O_AO + (size_t)r * cD + t] = a / den;
}

// ---------------- GAT kernels ----------------
__global__ void k_gat_init() {
    int i = blockIdx.x * blockDim.x + threadIdx.x;
    if (i < cTn * cNH) {
        g_m[i] = -INFINITY;
        g_den[i] = 0.f;
    }
}

__global__ void k_gat_logits(const float* __restrict__ asrc, const float* __restrict__ adst,
                             const float* __restrict__ aedge) {
    int idx = blockIdx.x * blockDim.x + threadIdx.x;
    if (idx >= cTe * cNH) return;
    int e = idx >> 3, h = idx & 7;
    int s = g_src[e], d2 = g_dst[e];
    int base = h * cDH;
    const float* hn = g_buf + O_HN;
    const float* ee = g_buf + O_EE;
    float sum = 0.f;
    #pragma unroll
    for (int d = 0; d < cDH; d++) {
        sum += hn[s * cD + base + d] * asrc[base + d]
             + hn[d2 * cD + base + d] * adst[base + d]
             + ee[e * cD + base + d] * aedge[base + d];
    }
    float lg = (sum > 0.f) ? sum : 0.2f * sum;
    g_logits[idx] = lg;
    atomicMaxF(&g_m[d2 * cNH + h], lg);
}

__global__ void k_gat_ex() {
    int idx = blockIdx.x * blockDim.x + threadIdx.x;
    if (idx >= cTe * cNH) return;
    int e = idx >> 3, h = idx & 7;
    int d2 = g_dst[e];
    float ex = expf(g_logits[idx] - g_m[d2 * cNH + h]);
    g_exl[idx] = ex;
    atomicAdd(&g_den[d2 * cNH + h], ex);
}

__global__ void k_gat_scatter() {
    int e = blockIdx.x;
    int c = threadIdx.x;
    int h = c >> 5;
    int d2 = g_dst[e], s = g_src[e];
    float alpha = g_exl[e * cNH + h] / (g_den[d2 * cNH + h] + 1e-9f);
    const float* hn = g_buf + O_HN;
    const float* ee = g_buf + O_EE;
    atomicAdd(&g_buf[O_NAGG + (size_t)d2 * cD + c],
              alpha * (hn[s * cD + c] + ee[e * cD + c]));
}

// ---------------- host orchestration ----------------
static void mma_nt_b(const float* A, const float* Bw, const float* bias, float* C,
                     int M, int N, int K) {
    dim3 gr(N / 64, M / 128);
    k_mma<true, true, false><<<gr, 256>>>(A, Bw, bias, C, M, N, K);
}
static void mma_nn_b(const float* A, const float* Bw, const float* bias, float* C,
                     int M, int N, int K) {
    dim3 gr(N / 64, M / 128);
    k_mma<false, true, false><<<gr, 256>>>(A, Bw, bias, C, M, N, K);
}
static void mma_nn_bg(const float* A, const float* Bw, const float* bias, float* C,
                      int M, int N, int K) {
    dim3 gr(N / 64, M / 128);
    k_mma<false, true, true><<<gr, 256>>>(A, Bw, bias, C, M, N, K);
}
static void mma_nn(const float* A, const float* Bw, float* C, int M, int N, int K) {
    dim3 gr(N / 64, M / 128);
    k_mma<false, false, false><<<gr, 256>>>(A, Bw, nullptr, C, M, N, K);
}

extern "C" void kernel_launch(void* const* d_in, const int* in_sizes, int n_in,
                              void* d_out, int out_size) {
    const float* features   = (const float*)d_in[0];
    const float* boxes      = (const float*)d_in[1];
    const int*   edge_local = (const int*)  d_in[2];
    const float* nodes0     = (const float*)d_in[3];
    const float* edges0     = (const float*)d_in[4];
    const float* ln1_g      = (const float*)d_in[5];
    const float* ln1_b      = (const float*)d_in[6];
    const float* attn_in_w  = (const float*)d_in[7];
    const float* attn_in_b  = (const float*)d_in[8];
    const float* attn_out_w = (const float*)d_in[9];
    const float* attn_out_b = (const float*)d_in[10];
    const float* ls1        = (const float*)d_in[11];
    const float* ln2_g      = (const float*)d_in[12];
    const float* ln2_b      = (const float*)d_in[13];
    const float* gat_wn     = (const float*)d_in[14];
    const float* gat_we     = (const float*)d_in[15];
    const float* gat_a_src  = (const float*)d_in[16];
    const float* gat_a_dst  = (const float*)d_in[17];
    const float* gat_a_edge = (const float*)d_in[18];
    const float* gat_wo     = (const float*)d_in[19];
    const float* gat_bo     = (const float*)d_in[20];
    const float* gat_woe    = (const float*)d_in[21];
    const float* gat_boe    = (const float*)d_in[22];
    const float* ls2        = (const float*)d_in[23];
    const float* ln3_g      = (const float*)d_in[24];
    const float* ln3_b      = (const float*)d_in[25];
    const float* ffn_w1     = (const float*)d_in[26];
    const float* ffn_b1     = (const float*)d_in[27];
    const float* ffn_w2     = (const float*)d_in[28];
    const float* ffn_b2     = (const float*)d_in[29];
    const float* ls3        = (const float*)d_in[30];

    float* buf = nullptr;
    cudaGetSymbolAddress((void**)&buf, g_buf);
    float* out = (float*)d_out;

    const int nTD = cT * cD;

    // -------- precompute --------
    k_edges<<<(cTe + 255) / 256, 256>>>(edge_local);
    k_node_heat<<<cTn, 256>>>(boxes);
    k_edge_heat<<<cTe, 256>>>(boxes);
    k_emb<<<nTD / 256, 256>>>(boxes);
    k_copy<<<(cTn * cD) / 256, 256>>>(buf + O_Q, nodes0, cTn * cD);
    k_copy<<<(cTe * cD) / 256, 256>>>(buf + O_Q + (size_t)cTn * cD, edges0, cTe * cD);

    for (int l = 0; l < cL; l++) {
        const float* Wqkv = attn_in_w + (size_t)l * 3 * cD * cD;
        const float* bqkv = attn_in_b + (size_t)l * 3 * cD;

        // ---- cross attention ----
        k_ln<<<cT, 256>>>(buf + O_Q, ln1_g + l * cD, ln1_b + l * cD, buf + O_X);
        mma_nt_b(buf + O_X, Wqkv, bqkv, buf + O_QH, cT, cD, cD);
        // packed K|V projection: N=512 (Wk rows then Wv rows are contiguous)
        mma_nt_b(features, Wqkv + cD * cD, bqkv + cD, buf + O_KH, cFKV, 512, cD);
        k_attn_partial<<<dim3(cNH, cB, SPLITS), 96>>>();
        k_attn_merge<<<dim3(cTB, cB), 256>>>();
        mma_nt_b(buf + O_AO, attn_out_w + (size_t)l * cD * cD,
                 attn_out_b + l * cD, buf + O_TMP, cT, cD, cD);
        k_res_add<<<nTD / 256, 256>>>(buf + O_Q, buf + O_TMP, ls1 + l * cD, nTD);

        // ---- GAT ----
        k_ln<<<cT, 256>>>(buf + O_Q, ln2_g + l * cD, ln2_b + l * cD, buf + O_X);
        k_vadd<<<nTD / 256, 256>>>(buf + O_XE, buf + O_X, buf + O_EMB, nTD);
        mma_nn(buf + O_XE, gat_wn + (size_t)l * cD * cD, buf + O_HN, cTn, cD, cD);
        mma_nn(buf + O_XE + (size_t)cTn * cD, gat_we + (size_t)l * cD * cD,
               buf + O_EE, cTe, cD, cD);
        k_gat_init<<<(cTn * cNH + 255) / 256, 256>>>();
        k_fill<<<(cTn * cD) / 256, 256>>>(buf + O_NAGG, 0.f, cTn * cD);
        k_gat_logits<<<(cTe * cNH) / 256, 256>>>(gat_a_src + l * cD, gat_a_dst + l * cD,
                                                 gat_a_edge + l * cD);
        k_gat_ex<<<(cTe * cNH) / 256, 256>>>();
        k_gat_scatter<<<cTe, 256>>>();
        mma_nn_b(buf + O_NAGG, gat_wo + (size_t)l * cD * cD, gat_bo + l * cD,
                 buf + O_TMP, cTn, cD, cD);
        mma_nn_b(buf + O_EE, gat_woe + (size_t)l * cD * cD, gat_boe + l * cD,
                 buf + O_TMP + (size_t)cTn * cD, cTe, cD, cD);
        k_res_fromx<<<nTD / 256, 256>>>(buf + O_Q, buf + O_X, buf + O_TMP, ls2 + l * cD, nTD);

        // ---- FFN ----
        k_ln<<<cT, 256>>>(buf + O_Q, ln3_g + l * cD, ln3_b + l * cD, buf + O_X);
        mma_nn_bg(buf + O_X, ffn_w1 + (size_t)l * cD * cFF, ffn_b1 + l * cFF,
                  buf + O_Y1, cT, cFF, cD);
        mma_nn_b(buf + O_Y1, ffn_w2 + (size_t)l * cFF * cD, ffn_b2 + l * cD,
                 buf + O_TMP, cT, cD, cFF);
        k_res_add<<<nTD / 256, 256>>>(buf + O_Q, buf + O_TMP, ls3 + l * cD, nTD);

        // ---- emit layer output ----
        k_copy<<<nTD / 256, 256>>>(out + (size_t)l * nTD, buf + O_Q, nTD);
    }
    (void)in_sizes; (void)n_in; (void)out_size;
}

// round 7
// speedup vs baseline: 1.9909x; 1.4786x over previous
#include <cuda_runtime.h>
#include <math.h>

// ---------------- constants ----------------
constexpr int cB = 32, cN = 32, cE = 64, cW = 40, cHgrid = 40, cHW = 1600;
constexpr int cD = 256, cNH = 8, cDH = 32, cL = 6;
constexpr int cTn = cB * cN;          // 1024
constexpr int cTe = cB * cE;          // 2048
constexpr int cT  = cTn + cTe;        // 3072
constexpr int cTB = cN + cE;          // 96 tokens per batch
constexpr int cFF = 1024;
constexpr int cFKV = cB * cHW;        // 51200
constexpr int SPLITS = 8;
constexpr int KSPLIT = cHW / SPLITS;  // 200
constexpr int KTILE = 64;
constexpr float ATTN_SCALE = 0.17677669529663689f; // 1/sqrt(32)
constexpr float LOG1E4 = 9.210340371976184f;

// ---------------- scratch arena ----------------
constexpr size_t SZ_TD = (size_t)cT * cD;           // 786432
constexpr size_t O_Q    = 0;
constexpr size_t O_X    = O_Q    + SZ_TD;
constexpr size_t O_XE   = O_X    + SZ_TD;
constexpr size_t O_TMP  = O_XE   + SZ_TD;
constexpr size_t O_QH   = O_TMP  + SZ_TD;
constexpr size_t O_AO   = O_QH   + SZ_TD;
constexpr size_t O_EMB  = O_AO   + SZ_TD;
constexpr size_t O_BIAS = O_EMB  + SZ_TD;                       // cT*cHW
constexpr size_t O_KH   = O_BIAS + (size_t)cT * cHW;            // cFKV*512 (packed K|V)
constexpr size_t O_Y1   = O_KH   + (size_t)cFKV * 512;          // cT*cFF
constexpr size_t O_HN   = O_Y1   + (size_t)cT * cFF;            // cTn*cD
constexpr size_t O_EE   = O_HN   + (size_t)cTn * cD;            // cTe*cD
constexpr size_t O_NAGG = O_EE   + (size_t)cTe * cD;            // cTn*cD
constexpr size_t O_PM   = O_NAGG + (size_t)cTn * cD;            // B*NH*TB*SPLITS
constexpr size_t SZ_P   = (size_t)cB * cNH * cTB * SPLITS;      // 196608
constexpr size_t O_PDEN = O_PM   + SZ_P;
constexpr size_t O_PACC = O_PDEN + SZ_P;                        // SZ_P*cDH
constexpr size_t O_TOTAL = O_PACC + SZ_P * cDH;

__device__ __align__(16) float g_buf[O_TOTAL];
__device__ int   g_src[cTe];
__device__ int   g_dst[cTe];
__device__ float g_logits[cTe * cNH];
__device__ float g_exl[cTe * cNH];
__device__ float g_m[cTn * cNH];
__device__ float g_den[cTn * cNH];

// ---------------- helpers ----------------
__device__ __forceinline__ int row_of(int b, int t) {
    return (t < cN) ? b * cN + t : cTn + b * cE + (t - cN);
}

__device__ __forceinline__ void atomicMaxF(float* addr, float val) {
    int old = __float_as_int(*addr);
    while (__int_as_float(old) < val) {
        int prev = atomicCAS((int*)addr, old, __float_as_int(val));
        if (prev == old) break;
        old = prev;
    }
}

__device__ __forceinline__ void mma8(float* c, const unsigned* a, const unsigned* b) {
    asm volatile(
        "mma.sync.aligned.m16n8k8.row.col.f32.tf32.tf32.f32 "
        "{%0,%1,%2,%3}, {%4,%5,%6,%7}, {%8,%9}, {%0,%1,%2,%3};"
        : "+f"(c[0]), "+f"(c[1]), "+f"(c[2]), "+f"(c[3])
        : "r"(a[0]), "r"(a[1]), "r"(a[2]), "r"(a[3]), "r"(b[0]), "r"(b[1]));
}

__device__ __forceinline__ void cpasync16(unsigned sa, const void* g) {
    asm volatile("cp.async.cg.shared.global [%0], [%1], 16;\n" :: "r"(sa), "l"(g));
}
__device__ __forceinline__ void cpcommit() { asm volatile("cp.async.commit_group;\n"); }
template <int W> __device__ __forceinline__ void cpwait() {
    asm volatile("cp.async.wait_group %0;\n" :: "n"(W));
}

__device__ __forceinline__ unsigned long long ffma2(unsigned long long a,
                                                    unsigned long long b,
                                                    unsigned long long c) {
    unsigned long long d;
    asm("fma.rn.f32x2 %0, %1, %2, %3;" : "=l"(d) : "l"(a), "l"(b), "l"(c));
    return d;
}
__device__ __forceinline__ unsigned long long pack2(float lo, float hi) {
    unsigned long long d;
    asm("mov.b64 %0, {%1, %2};" : "=l"(d) : "f"(lo), "f"(hi));
    return d;
}
__device__ __forceinline__ float2 unpack2(unsigned long long v) {
    float lo, hi;
    asm("mov.b64 {%0, %1}, %2;" : "=f"(lo), "=f"(hi) : "l"(v));
    return make_float2(lo, hi);
}

// ---------------- precompute kernels ----------------
__global__ void k_edges(const int* __restrict__ el) {
    int e = blockIdx.x * blockDim.x + threadIdx.x;
    if (e < cTe) {
        int b = e / cE;
        g_src[e] = el[e] + b * cN;
        g_dst[e] = el[cTe + e] + b * cN;
    }
}

__global__ void k_node_heat(const float* __restrict__ boxes) {
    int nd = blockIdx.x;
    int t = threadIdx.x;
    __shared__ float hx[cW], hy[cHgrid];
    float cx = boxes[nd * 4 + 0], cy = boxes[nd * 4 + 1];
    float w  = boxes[nd * 4 + 2], h  = boxes[nd * 4 + 3];
    if (t < cW) {
        float gx = (t + 0.5f) / cW;
        float dd = gx - cx;
        hx[t] = expf(-dd * dd / (0.5f * w * w + 1e-6f));
    } else if (t < cW + cHgrid) {
        int y = t - cW;
        float gy = (y + 0.5f) / cHgrid;
        float dd = gy - cy;
        hy[y] = expf(-dd * dd / (0.5f * h * h + 1e-6f));
    }
    __syncthreads();
    float* out = g_buf + O_BIAS + (size_t)nd * cHW;
    for (int i = t; i < cHW; i += blockDim.x)
        out[i] = hy[i / cW] * hx[i % cW];
}

__global__ void k_edge_heat(const float* __restrict__ boxes) {
    int e = blockIdx.x;
    int t = threadIdx.x;
    int s = g_src[e], d = g_dst[e];
    float c1x = boxes[s*4+0], c1y = boxes[s*4+1], w1 = boxes[s*4+2], h1 = boxes[s*4+3];
    float c2x = boxes[d*4+0], c2y = boxes[d*4+1], w2 = boxes[d*4+2], h2 = boxes[d*4+3];
    float ux1 = fminf(c1x - w1*0.5f, c2x - w2*0.5f);
    float uy1 = fminf(c1y - h1*0.5f, c2y - h2*0.5f);
    float ux2 = fmaxf(c1x + w1*0.5f, c2x + w2*0.5f);
    float uy2 = fmaxf(c1y + h1*0.5f, c2y + h2*0.5f);
    float ucx = (ux1 + ux2) * 0.5f, ucy = (uy1 + uy2) * 0.5f;
    float uw = ux2 - ux1, uh = uy2 - uy1;
    __shared__ float hx[cW], hy[cHgrid];
    if (t < cW) {
        float gx = (t + 0.5f) / cW;
        float dd = gx - ucx;
        hx[t] = expf(-dd * dd / (0.5f * uw * uw + 1e-6f));
    } else if (t < cW + cHgrid) {
        int y = t - cW;
        float gy = (y + 0.5f) / cHgrid;
        float dd = gy - ucy;
        hy[y] = expf(-dd * dd / (0.5f * uh * uh + 1e-6f));
    }
    __syncthreads();
    const float* hs = g_buf + O_BIAS + (size_t)s * cHW;
    const float* hd = g_buf + O_BIAS + (size_t)d * cHW;
    float* out = g_buf + O_BIAS + (size_t)(cTn + e) * cHW;
    for (int i = t; i < cHW; i += blockDim.x) {
        float u = hy[i / cW] * hx[i % cW];
        out[i] = fmaxf(fmaxf(hs[i], hd[i]), u);
    }
}

__global__ void k_emb(const float* __restrict__ boxes) {
    int i = blockIdx.x * blockDim.x + threadIdx.x;
    if (i >= cT * cD) return;
    int r = i / cD, ch = i % cD;
    int c = ch >> 6;
    int j = ch & 63;
    int fj = j & 31;
    float v;
    if (r < cTn) {
        v = boxes[r * 4 + c];
    } else {
        int e = r - cTn;
        v = boxes[g_src[e] * 4 + c] - boxes[g_dst[e] * 4 + c];
    }
    float fr = expf(-LOG1E4 * (float)fj / 32.0f);
    float ang = v * fr;
    g_buf[O_EMB + i] = (j < 32) ? sinf(ang) : cosf(ang);
}

// ---------------- generic kernels ----------------
__global__ void k_copy(float* __restrict__ dst, const float* __restrict__ src, int n) {
    int i = blockIdx.x * blockDim.x + threadIdx.x;
    if (i < n) dst[i] = src[i];
}

// LayerNorm: warp per row, 8 rows/block; optional xe = out + emb second output.
__global__ void __launch_bounds__(256) k_ln(const float* __restrict__ in,
                                            const float* __restrict__ gg,
                                            const float* __restrict__ bt,
                                            float* __restrict__ out,
                                            float* __restrict__ xe,
                                            const float* __restrict__ emb) {
    int warp = threadIdx.x >> 5, lane = threadIdx.x & 31;
    size_t r = (size_t)blockIdx.x * 8 + warp;
    const float4* row = (const float4*)(in + r * cD);
    float4 v0 = row[lane * 2], v1 = row[lane * 2 + 1];
    float s = v0.x + v0.y + v0.z + v0.w + v1.x + v1.y + v1.z + v1.w;
    #pragma unroll
    for (int o = 16; o; o >>= 1) s += __shfl_xor_sync(0xffffffffu, s, o);
    float mean = s * (1.0f / cD);
    v0.x -= mean; v0.y -= mean; v0.z -= mean; v0.w -= mean;
    v1.x -= mean; v1.y -= mean; v1.z -= mean; v1.w -= mean;
    float s2 = v0.x*v0.x + v0.y*v0.y + v0.z*v0.z + v0.w*v0.w
             + v1.x*v1.x + v1.y*v1.y + v1.z*v1.z + v1.w*v1.w;
    #pragma unroll
    for (int o = 16; o; o >>= 1) s2 += __shfl_xor_sync(0xffffffffu, s2, o);
    float inv = rsqrtf(s2 * (1.0f / cD) + 1e-5f);
    const float4* g4 = (const float4*)gg;
    const float4* b4 = (const float4*)bt;
    float4 ga = g4[lane * 2], gb = g4[lane * 2 + 1];
    float4 ba = b4[lane * 2], bb = b4[lane * 2 + 1];
    float4 o0, o1;
    o0.x = v0.x * inv * ga.x + ba.x; o0.y = v0.y * inv * ga.y + ba.y;
    o0.z = v0.z * inv * ga.z + ba.z; o0.w = v0.w * inv * ga.w + ba.w;
    o1.x = v1.x * inv * gb.x + bb.x; o1.y = v1.y * inv * gb.y + bb.y;
    o1.z = v1.z * inv * gb.z + bb.z; o1.w = v1.w * inv * gb.w + bb.w;
    float4* po = (float4*)(out + r * cD);
    po[lane * 2] = o0; po[lane * 2 + 1] = o1;
    if (xe) {
        const float4* e4 = (const float4*)(emb + r * cD);
        float4 e0 = e4[lane * 2], e1 = e4[lane * 2 + 1];
        float4 x0, x1;
        x0.x = o0.x + e0.x; x0.y = o0.y + e0.y; x0.z = o0.z + e0.z; x0.w = o0.w + e0.w;
        x1.x = o1.x + e1.x; x1.y = o1.y + e1.y; x1.z = o1.z + e1.z; x1.w = o1.w + e1.w;
        float4* px = (float4*)(xe + r * cD);
        px[lane * 2] = x0; px[lane * 2 + 1] = x1;
    }
}

// ---------------- tf32 tensor-core GEMM, cp.async double-buffered ----------------
// C[M,N] = A[M,K] * op(B); TB: B is [N,K] (op=B^T); !TB: B is [K,N].
// EPI: 0=none, 1=+bias, 2=+bias,gelu, 3: C += ls*(v+bias) (opt dual store D2),
//      4: C = X + ls*(v+bias)
// Tiles 128x64x16, 256 threads, 8 warps (4M x 2N), warp=32x32.
template <bool TB, int EPI>
__global__ void __launch_bounds__(256) k_mma(const float* __restrict__ A,
                                             const float* __restrict__ Bw,
                                             const float* __restrict__ bias,
                                             float* __restrict__ C,
                                             const float* __restrict__ X,
                                             const float* __restrict__ ls,
                                             float* __restrict__ D2,
                                             int M, int N, int K) {
    constexpr int BR = TB ? 64 : 16;
    constexpr int BC = TB ? 20 : 68;
    __shared__ float As[2][128][20];
    __shared__ float Bs[2][BR][BC];
    const int tid = threadIdx.x;
    const int m0 = blockIdx.y * 128, n0 = blockIdx.x * 64;
    const int wid = tid >> 5, lane = tid & 31;
    const int wm = (wid & 3) * 32, wn = (wid >> 2) * 32;
    const int g = lane >> 2, tg = lane & 3;
    float c[2][4][4] = {};

    auto loadA = [&](int st, int k0) {
        #pragma unroll
        for (int h = 0; h < 2; h++) {
            int idx = tid + h * 256;
            int row = idx >> 2, c4 = idx & 3;
            unsigned sa = (unsigned)__cvta_generic_to_shared(&As[st][row][c4 * 4]);
            cpasync16(sa, A + (size_t)(m0 + row) * K + k0 + c4 * 4);
        }
    };
    auto loadB = [&](int st, int k0) {
        if constexpr (TB) {
            int row = tid >> 2, c4 = tid & 3;
            unsigned sa = (unsigned)__cvta_generic_to_shared(&Bs[st][row][c4 * 4]);
            cpasync16(sa, Bw + (size_t)(n0 + row) * K + k0 + c4 * 4);
        } else {
            int row = tid >> 4, c4 = tid & 15;
            unsigned sa = (unsigned)__cvta_generic_to_shared(&Bs[st][row][c4 * 4]);
            cpasync16(sa, Bw + (size_t)(k0 + row) * N + n0 + c4 * 4);
        }
    };

    const int T = K >> 4;
    loadA(0, 0); loadB(0, 0); cpcommit();
    for (int it = 0; it < T; it++) {
        int st = it & 1;
        if (it + 1 < T) {
            loadA(st ^ 1, (it + 1) * 16);
            loadB(st ^ 1, (it + 1) * 16);
            cpcommit();
            cpwait<1>();
        } else {
            cpwait<0>();
        }
        __syncthreads();
        #pragma unroll
        for (int kk = 0; kk < 16; kk += 8) {
            unsigned a[2][4], b[4][2];
            #pragma unroll
            for (int i = 0; i < 2; i++) {
                int m = wm + i * 16 + g;
                a[i][0] = __float_as_uint(As[st][m][kk + tg]);
                a[i][1] = __float_as_uint(As[st][m + 8][kk + tg]);
                a[i][2] = __float_as_uint(As[st][m][kk + tg + 4]);
                a[i][3] = __float_as_uint(As[st][m + 8][kk + tg + 4]);
            }
            #pragma unroll
            for (int j = 0; j < 4; j++) {
                int n = wn + j * 8 + g;
                if constexpr (TB) {
                    b[j][0] = __float_as_uint(Bs[st][n][kk + tg]);
                    b[j][1] = __float_as_uint(Bs[st][n][kk + tg + 4]);
                } else {
                    b[j][0] = __float_as_uint(Bs[st][kk + tg][n]);
                    b[j][1] = __float_as_uint(Bs[st][kk + tg + 4][n]);
                }
            }
            #pragma unroll
            for (int i = 0; i < 2; i++)
                #pragma unroll
                for (int j = 0; j < 4; j++)
                    mma8(c[i][j], a[i], b[j]);
        }
        __syncthreads();
    }
    #pragma unroll
    for (int i = 0; i < 2; i++) {
        #pragma unroll
        for (int j = 0; j < 4; j++) {
            int col = n0 + wn + j * 8 + tg * 2;
            #pragma unroll
            for (int p = 0; p < 4; p++) {
                int row = m0 + wm + i * 16 + g + ((p >= 2) ? 8 : 0);
                int cc = col + (p & 1);
                float v = c[i][j][p];
                if (EPI >= 1 && EPI != 0) v += bias[cc];
                if (EPI == 2) v = 0.5f * v * (1.0f + erff(v * 0.70710678118654752f));
                size_t idx = (size_t)row * N + cc;
                if (EPI == 3) {
                    float nv = C[idx] + ls[cc] * v;
                    C[idx] = nv;
                    if (D2) D2[idx] = nv;
                } else if (EPI == 4) {
                    C[idx] = X[idx] + ls[cc] * v;
                } else {
                    C[idx] = v;
                }
            }
        }
    }
}

// ---------------- attention (flash-style, key-split, f32x2 packed) ----------------
// K/V packed: row stride 512 floats, K at +0, V at +256
__global__ void __launch_bounds__(96) k_attn_partial() {
    int h = blockIdx.x, b = blockIdx.y, s = blockIdx.z;
    int q = threadIdx.x; // 0..95
    __shared__ __align__(16) float ks[KTILE][32];
    __shared__ __align__(16) float vs[KTILE][32];
    const float* khv = g_buf + O_KH;
    int r = row_of(b, q);
    unsigned long long q2[16];
    {
        const float2* qp = (const float2*)(g_buf + O_QH + (size_t)r * cD + h * cDH);
        #pragma unroll
        for (int d = 0; d < 16; d++) { float2 t = qp[d]; q2[d] = pack2(t.x, t.y); }
    }
    const float* brow = g_buf + O_BIAS + (size_t)r * cHW;
    float m = -INFINITY, den = 0.f;
    unsigned long long acc[16];
    #pragma unroll
    for (int d = 0; d < 16; d++) acc[d] = 0ull;
    int kbeg = s * KSPLIT;
    for (int k0 = kbeg; k0 < kbeg + KSPLIT; k0 += KTILE) {
        int kt = min(KTILE, kbeg + KSPLIT - k0);
        __syncthreads();
        for (int idx = q; idx < kt * 8; idx += 96) {
            int kk = idx >> 3, d4 = idx & 7;
            const float4* src = (const float4*)(khv + (size_t)(b * cHW + k0 + kk) * 512
                                                + h * cDH + d4 * 4);
            *(float4*)&ks[kk][d4 * 4] = src[0];
            *(float4*)&vs[kk][d4 * 4] = *(const float4*)((const float*)src + 256);
        }
        __syncthreads();
        for (int kk = 0; kk < kt; kk += 4) {
            float4 b4 = *(const float4*)(brow + k0 + kk);
            float bb[4] = {b4.x, b4.y, b4.z, b4.w};
            #pragma unroll
            for (int u = 0; u < 4; u++) {
                const ulonglong2* kp = (const ulonglong2*)ks[kk + u];
                unsigned long long da = 0ull, db = 0ull;
                #pragma unroll
                for (int d = 0; d < 8; d++) {
                    ulonglong2 kv = kp[d];
                    da = ffma2(q2[2 * d], kv.x, da);
                    db = ffma2(q2[2 * d + 1], kv.y, db);
                }
                float2 dra = unpack2(da), drb = unpack2(db);
                float sc = (dra.x + dra.y + drb.x + drb.y) * ATTN_SCALE + bb[u];
                const ulonglong2* vp = (const ulonglong2*)vs[kk + u];
                if (sc <= m) {
                    float p = __expf(sc - m);
                    den += p;
                    unsigned long long p2 = pack2(p, p);
                    #pragma unroll
                    for (int d = 0; d < 8; d++) {
                        ulonglong2 vv = vp[d];
                        acc[2 * d]     = ffma2(p2, vv.x, acc[2 * d]);
                        acc[2 * d + 1] = ffma2(p2, vv.y, acc[2 * d + 1]);
                    }
                } else {
                    float cc = __expf(m - sc);
                    m = sc;
                    den = den * cc + 1.f;
                    unsigned long long c2 = pack2(cc, cc);
                    #pragma unroll
                    for (int d = 0; d < 8; d++) {
                        ulonglong2 vv = vp[d];
                        acc[2 * d]     = ffma2(acc[2 * d], c2, vv.x);
                        acc[2 * d + 1] = ffma2(acc[2 * d + 1], c2, vv.y);
                    }
                }
            }
        }
    }
    int pidx = ((b * cNH + h) * cTB + q) * SPLITS + s;
    g_buf[O_PM + pidx] = m;
    g_buf[O_PDEN + pidx] = den;
    float* pa = g_buf + O_PACC + (size_t)pidx * cDH;
    #pragma unroll
    for (int d = 0; d < 16; d++) {
        float2 t = unpack2(acc[d]);
        pa[2 * d] = t.x;
        pa[2 * d + 1] = t.y;
    }
}

__global__ void k_attn_merge() {
    int q = blockIdx.x, b = blockIdx.y;
    int t = threadIdx.x;
    int h = t >> 5, d = t & 31;
    int base = ((b * cNH + h) * cTB + q) * SPLITS;
    float M = -INFINITY;
    #pragma unroll
    for (int s = 0; s < SPLITS; s++) M = fmaxf(M, g_buf[O_PM + base + s]);
    float den = 0.f, a = 0.f;
    #pragma unroll
    for (int s = 0; s < SPLITS; s++) {
        float w = __expf(g_buf[O_PM + base + s] - M);
        den += g_buf[O_PDEN + base + s] * w;
        a += g_buf[O_PACC + (size_t)(base + s) * cDH + d] * w;
    }
    int r = row_of(b, q);
    g_buf[O_AO + (size_t)r * cD + t] = a / den;
}

// ---------------- GAT kernels ----------------
__global__ void k_gat_init() {
    int i = blockIdx.x * blockDim.x + threadIdx.x;
    if (i < cTn * cNH) {
        g_m[i] = -INFINITY;
        g_den[i] = 0.f;
    }
    if (i < cTn * cD) g_buf[O_NAGG + i] = 0.f;
}

__global__ void k_gat_logits(const float* __restrict__ asrc, const float* __restrict__ adst,
                             const float* __restrict__ aedge) {
    int idx = blockIdx.x * blockDim.x + threadIdx.x;
    if (idx >= cTe * cNH) return;
    int e = idx >> 3, h = idx & 7;
    int s = g_src[e], d2 = g_dst[e];
    int base = h * cDH;
    const float* hn = g_buf + O_HN;
    const float* ee = g_buf + O_EE;
    float sum = 0.f;
    #pragma unroll
    for (int d = 0; d < cDH; d++) {
        sum += hn[s * cD + base + d] * asrc[base + d]
             + hn[d2 * cD + base + d] * adst[base + d]
             + ee[e * cD + base + d] * aedge[base + d];
    }
    float lg = (sum > 0.f) ? sum : 0.2f * sum;
    g_logits[idx] = lg;
    atomicMaxF(&g_m[d2 * cNH + h], lg);
}

__global__ void k_gat_ex() {
    int idx = blockIdx.x * blockDim.x + threadIdx.x;
    if (idx >= cTe * cNH) return;
    int e = idx >> 3, h = idx & 7;
    int d2 = g_dst[e];
    float ex = expf(g_logits[idx] - g_m[d2 * cNH + h]);
    g_exl[idx] = ex;
    atomicAdd(&g_den[d2 * cNH + h], ex);
}

__global__ void k_gat_scatter() {
    int e = blockIdx.x;
    int c = threadIdx.x;
    int h = c >> 5;
    int d2 = g_dst[e], s = g_src[e];
    float alpha = g_exl[e * cNH + h] / (g_den[d2 * cNH + h] + 1e-9f);
    const float* hn = g_buf + O_HN;
    const float* ee = g_buf + O_EE;
    atomicAdd(&g_buf[O_NAGG + (size_t)d2 * cD + c],
              alpha * (hn[s * cD + c] + ee[e * cD + c]));
}

// ---------------- host orchestration ----------------
extern "C" void kernel_launch(void* const* d_in, const int* in_sizes, int n_in,
                              void* d_out, int out_size) {
    const float* features   = (const float*)d_in[0];
    const float* boxes      = (const float*)d_in[1];
    const int*   edge_local = (const int*)  d_in[2];
    const float* nodes0     = (const float*)d_in[3];
    const float* edges0     = (const float*)d_in[4];
    const float* ln1_g      = (const float*)d_in[5];
    const float* ln1_b      = (const float*)d_in[6];
    const float* attn_in_w  = (const float*)d_in[7];
    const float* attn_in_b  = (const float*)d_in[8];
    const float* attn_out_w = (const float*)d_in[9];
    const float* attn_out_b = (const float*)d_in[10];
    const float* ls1        = (const float*)d_in[11];
    const float* ln2_g      = (const float*)d_in[12];
    const float* ln2_b      = (const float*)d_in[13];
    const float* gat_wn     = (const float*)d_in[14];
    const float* gat_we     = (const float*)d_in[15];
    const float* gat_a_src  = (const float*)d_in[16];
    const float* gat_a_dst  = (const float*)d_in[17];
    const float* gat_a_edge = (const float*)d_in[18];
    const float* gat_wo     = (const float*)d_in[19];
    const float* gat_bo     = (const float*)d_in[20];
    const float* gat_woe    = (const float*)d_in[21];
    const float* gat_boe    = (const float*)d_in[22];
    const float* ls2        = (const float*)d_in[23];
    const float* ln3_g      = (const float*)d_in[24];
    const float* ln3_b      = (const float*)d_in[25];
    const float* ffn_w1     = (const float*)d_in[26];
    const float* ffn_b1     = (const float*)d_in[27];
    const float* ffn_w2     = (const float*)d_in[28];
    const float* ffn_b2     = (const float*)d_in[29];
    const float* ls3        = (const float*)d_in[30];

    float* buf = nullptr;
    cudaGetSymbolAddress((void**)&buf, g_buf);
    float* out = (float*)d_out;

    const int nTD = cT * cD;

    // -------- precompute --------
    k_edges<<<(cTe + 255) / 256, 256>>>(edge_local);
    k_node_heat<<<cTn, 256>>>(boxes);
    k_edge_heat<<<cTe, 256>>>(boxes);
    k_emb<<<nTD / 256, 256>>>(boxes);
    k_copy<<<(cTn * cD) / 256, 256>>>(buf + O_Q, nodes0, cTn * cD);
    k_copy<<<(cTe * cD) / 256, 256>>>(buf + O_Q + (size_t)cTn * cD, edges0, cTe * cD);

    for (int l = 0; l < cL; l++) {
        const float* Wqkv = attn_in_w + (size_t)l * 3 * cD * cD;
        const float* bqkv = attn_in_b + (size_t)l * 3 * cD;

        // ---- cross attention ----
        k_ln<<<cT / 8, 256>>>(buf + O_Q, ln1_g + l * cD, ln1_b + l * cD,
                              buf + O_X, nullptr, nullptr);
        k_mma<true, 1><<<dim3(cD / 64, cT / 128), 256>>>(
            buf + O_X, Wqkv, bqkv, buf + O_QH, nullptr, nullptr, nullptr, cT, cD, cD);
        // packed K|V projection: N=512 (Wk rows then Wv rows contiguous)
        k_mma<true, 1><<<dim3(512 / 64, cFKV / 128), 256>>>(
            features, Wqkv + cD * cD, bqkv + cD, buf + O_KH,
            nullptr, nullptr, nullptr, cFKV, 512, cD);
        k_attn_partial<<<dim3(cNH, cB, SPLITS), 96>>>();
        k_attn_merge<<<dim3(cTB, cB), 256>>>();
        // attn_out fused residual: Q += ls1 * (AO @ W^T + b)
        k_mma<true, 3><<<dim3(cD / 64, cT / 128), 256>>>(
            buf + O_AO, attn_out_w + (size_t)l * cD * cD, attn_out_b + l * cD,
            buf + O_Q, nullptr, ls1 + l * cD, nullptr, cT, cD, cD);

        // ---- GAT ----
        k_ln<<<cT / 8, 256>>>(buf + O_Q, ln2_g + l * cD, ln2_b + l * cD,
                              buf + O_X, buf + O_XE, buf + O_EMB);
        k_mma<false, 0><<<dim3(cD / 64, cTn / 128), 256>>>(
            buf + O_XE, gat_wn + (size_t)l * cD * cD, nullptr, buf + O_HN,
            nullptr, nullptr, nullptr, cTn, cD, cD);
        k_mma<false, 0><<<dim3(cD / 64, cTe / 128), 256>>>(
            buf + O_XE + (size_t)cTn * cD, gat_we + (size_t)l * cD * cD, nullptr,
            buf + O_EE, nullptr, nullptr, nullptr, cTe, cD, cD);
        k_gat_init<<<(cTn * cD) / 256, 256>>>();
        k_gat_logits<<<(cTe * cNH) / 256, 256>>>(gat_a_src + l * cD, gat_a_dst + l * cD,
                                                 gat_a_edge + l * cD);
        k_gat_ex<<<(cTe * cNH) / 256, 256>>>();
        k_gat_scatter<<<cTe, 256>>>();
        // fused: Q = X + ls2 * (NAGG @ Wo + bo)   rows [0, Tn)
        k_mma<false, 4><<<dim3(cD / 64, cTn / 128), 256>>>(
            buf + O_NAGG, gat_wo + (size_t)l * cD * cD, gat_bo + l * cD,
            buf + O_Q, buf + O_X, ls2 + l * cD, nullptr, cTn, cD, cD);
        // fused: Q = X + ls2 * (EE @ Woe + boe)   rows [Tn, T)
        k_mma<false, 4><<<dim3(cD / 64, cTe / 128), 256>>>(
            buf + O_EE, gat_woe + (size_t)l * cD * cD, gat_boe + l * cD,
            buf + O_Q + (size_t)cTn * cD, buf + O_X + (size_t)cTn * cD,
            ls2 + l * cD, nullptr, cTe, cD, cD);

        // ---- FFN ----
        k_ln<<<cT / 8, 256>>>(buf + O_Q, ln3_g + l * cD, ln3_b + l * cD,
                              buf + O_X, nullptr, nullptr);
        k_mma<false, 2><<<dim3(cFF / 64, cT / 128), 256>>>(
            buf + O_X, ffn_w1 + (size_t)l * cD * cFF, ffn_b1 + l * cFF,
            buf + O_Y1, nullptr, nullptr, nullptr, cT, cFF, cD);
        // ffn2 fused residual + dual store (emits layer output)
        k_mma<false, 3><<<dim3(cD / 64, cT / 128), 256>>>(
            buf + O_Y1, ffn_w2 + (size_t)l * cFF * cD, ffn_b2 + l * cD,
            buf + O_Q, nullptr, ls3 + l * cD, out + (size_t)l * nTD, cT, cD, cFF);
    }
    (void)in_sizes; (void)n_in; (void)out_size;
}